// round 4
// baseline (speedup 1.0000x reference)
#include <cuda_runtime.h>
#include <cuda_bf16.h>
#include <math.h>

// Problem constants
#define BB 64
#define TT 1024
#define QD 1024
#define CD 512
#define SPLITS 16
#define TCHUNK (TT / SPLITS)   // 64
#define NTHR 128

// Output layout (float32): context[B,CD] | a[B,T] | u_new[B] | sq_new[B]
#define CTX_OFF 0
#define A_OFF   (BB * CD)                 // 32768
#define U_OFF   (A_OFF + BB * TT)         // 98304
#define SQ_OFF  (U_OFF + BB)              // 98368

// Scratch: partial (unnormalized) contexts + per-batch completion counters.
__device__ float        g_partial[BB * SPLITS * CD];
__device__ unsigned int g_cnt[BB];   // zero-init; reducer resets -> replay-safe

__device__ __forceinline__ float block_sum_128(float v, float* red)
{
    const int lane = threadIdx.x & 31;
    const int wid  = threadIdx.x >> 5;
    #pragma unroll
    for (int o = 16; o > 0; o >>= 1) v += __shfl_xor_sync(0xffffffffu, v, o);
    if (lane == 0) red[wid] = v;
    __syncthreads();
    float r = red[0] + red[1] + red[2] + red[3];
    __syncthreads();
    return r;
}

// ---------------------------------------------------------------------------
// Single fused kernel. Grid (SPLITS, B), 128 threads.
// Phase 1 (all blocks): compute unnormalized v for this chunk, write to 'a'
// region, float4 matvec vs inputs -> partial context. Fence + ticket.
// Phase 2 (one block per batch, the last to finish): normalize, reduce
// partials -> context, rescale 'a', sigmoid heads.
// ---------------------------------------------------------------------------
__global__ void __launch_bounds__(NTHR) k_fused(
    const float* __restrict__ inputs,
    const float* __restrict__ alpha,
    const float* __restrict__ u,
    const float* __restrict__ sq,
    const float* __restrict__ query,
    const float* __restrict__ W_u,  const float* __restrict__ b_u,
    const float* __restrict__ W_sq, const float* __restrict__ b_sq,
    float* __restrict__ out,
    float* __restrict__ partial,
    unsigned int* __restrict__ cnt)
{
    const int s   = blockIdx.x;
    const int b   = blockIdx.y;
    const int tid = threadIdx.x;
    const int t0  = s * TCHUNK;

    __shared__ float sa[TCHUNK];
    __shared__ float red[4];
    __shared__ unsigned int ticket;

    // --- Phase 1a: alpha chunk (threads 0..63) ---
    if (tid < TCHUNK) {
        const int t = t0 + tid;
        const float ub  = u[b];
        const float sqb = sq[b];
        const float* arow = alpha + (size_t)b * TT;
        const float cur  = arow[t];
        const float prev = (t > 0) ? arow[t - 1] : 0.0f;
        const float base = fmaf(-ub, cur, cur) + fmaf(ub, prev, 1e-6f);
        const float v = __expf(sqb * __logf(base));   // base > 0 always
        sa[tid] = v;
        out[A_OFF + (size_t)b * TT + t] = v;          // unnormalized; reducer rescales
    }
    __syncthreads();

    // --- Phase 1b: float4 matvec over this chunk ---
    const float4* __restrict__ inp =
        (const float4*)(inputs + ((size_t)b * TT + t0) * CD) + tid;

    float4 a0 = {0,0,0,0}, a1 = {0,0,0,0}, a2 = {0,0,0,0}, a3 = {0,0,0,0};
    #pragma unroll 4
    for (int i = 0; i < TCHUNK; i += 4) {
        const float4 v0 = __ldcs(&inp[(size_t)(i + 0) * (CD/4)]);
        const float4 v1 = __ldcs(&inp[(size_t)(i + 1) * (CD/4)]);
        const float4 v2 = __ldcs(&inp[(size_t)(i + 2) * (CD/4)]);
        const float4 v3 = __ldcs(&inp[(size_t)(i + 3) * (CD/4)]);
        const float w0 = sa[i + 0], w1 = sa[i + 1], w2 = sa[i + 2], w3 = sa[i + 3];
        a0.x = fmaf(w0, v0.x, a0.x); a0.y = fmaf(w0, v0.y, a0.y);
        a0.z = fmaf(w0, v0.z, a0.z); a0.w = fmaf(w0, v0.w, a0.w);
        a1.x = fmaf(w1, v1.x, a1.x); a1.y = fmaf(w1, v1.y, a1.y);
        a1.z = fmaf(w1, v1.z, a1.z); a1.w = fmaf(w1, v1.w, a1.w);
        a2.x = fmaf(w2, v2.x, a2.x); a2.y = fmaf(w2, v2.y, a2.y);
        a2.z = fmaf(w2, v2.z, a2.z); a2.w = fmaf(w2, v2.w, a2.w);
        a3.x = fmaf(w3, v3.x, a3.x); a3.y = fmaf(w3, v3.y, a3.y);
        a3.z = fmaf(w3, v3.z, a3.z); a3.w = fmaf(w3, v3.w, a3.w);
    }
    float4 r;
    r.x = (a0.x + a1.x) + (a2.x + a3.x);
    r.y = (a0.y + a1.y) + (a2.y + a3.y);
    r.z = (a0.z + a1.z) + (a2.z + a3.z);
    r.w = (a0.w + a1.w) + (a2.w + a3.w);
    ((float4*)(partial + ((size_t)b * SPLITS + s) * CD))[tid] = r;

    // --- publish + ticket ---
    __threadfence();
    if (tid == 0) ticket = atomicAdd(&cnt[b], 1u);
    __syncthreads();
    if (ticket != SPLITS - 1) return;

    // ======================= Phase 2: reducer for batch b ==================
    if (tid == 0) cnt[b] = 0u;        // reset for next graph replay
    __threadfence();                   // acquire: see peers' writes

    // total v-sum from the 'a' region
    float sl = 0.0f;
    #pragma unroll
    for (int t = tid; t < TT; t += NTHR)
        sl += out[A_OFF + (size_t)b * TT + t];
    const float S   = block_sum_128(sl, red);
    const float inv = 1.0f / S;

    // rescale 'a' in place
    #pragma unroll
    for (int t = tid; t < TT; t += NTHR)
        out[A_OFF + (size_t)b * TT + t] *= inv;

    // reduce partials -> normalized context (keep in smem for the heads)
    __shared__ float sctx[CD];
    #pragma unroll
    for (int c = tid; c < CD; c += NTHR) {
        float acc = 0.0f;
        #pragma unroll
        for (int k = 0; k < SPLITS; k++)
            acc += partial[((size_t)b * SPLITS + k) * CD + c];
        const float ctx = acc * inv;
        sctx[c] = ctx;
        out[CTX_OFF + (size_t)b * CD + c] = ctx;
    }
    __syncthreads();

    // heads: ta = [context(512), query(1024)]
    float pu = 0.0f, ps = 0.0f;
    #pragma unroll
    for (int i = tid; i < CD; i += NTHR) {
        const float c = sctx[i];
        pu = fmaf(c, W_u[i],  pu);
        ps = fmaf(c, W_sq[i], ps);
    }
    #pragma unroll
    for (int i = tid; i < QD; i += NTHR) {
        const float q = query[(size_t)b * QD + i];
        pu = fmaf(q, W_u[CD + i],  pu);
        ps = fmaf(q, W_sq[CD + i], ps);
    }
    const float PU = block_sum_128(pu, red);
    const float PS = block_sum_128(ps, red);
    if (tid == 0) {
        out[U_OFF + b]  = 1.0f / (1.0f + expf(-(PU + b_u[0])));
        out[SQ_OFF + b] = 1.0f / (1.0f + expf(-(PS + b_sq[0]))) + 1.0f;
    }
}

extern "C" void kernel_launch(void* const* d_in, const int* in_sizes, int n_in,
                              void* d_out, int out_size)
{
    const float* query  = (const float*)d_in[0];  // [B,1,QD]
    const float* inputs = (const float*)d_in[1];  // [B,T,CD]
    const float* alpha  = (const float*)d_in[2];  // [B,T]
    const float* u      = (const float*)d_in[3];  // [B,1]
    const float* sq     = (const float*)d_in[4];  // [B,1]
    const float* W_u    = (const float*)d_in[5];  // [QD+CD,1]
    const float* b_u    = (const float*)d_in[6];  // [1]
    const float* W_sq   = (const float*)d_in[7];  // [QD+CD,1]
    const float* b_sq   = (const float*)d_in[8];  // [1]
    float* out = (float*)d_out;

    float* partial;
    unsigned int* cnt;
    cudaGetSymbolAddress((void**)&partial, g_partial);
    cudaGetSymbolAddress((void**)&cnt, g_cnt);

    dim3 g(SPLITS, BB);
    k_fused<<<g, NTHR>>>(inputs, alpha, u, sq, query,
                         W_u, b_u, W_sq, b_sq,
                         out, partial, cnt);
}

// round 5
// speedup vs baseline: 1.1349x; 1.1349x over previous
#include <cuda_runtime.h>
#include <cuda_bf16.h>
#include <math.h>

// Problem constants
#define BB 64
#define TT 1024
#define QD 1024
#define CD 512
#define SPLITS 16
#define TCHUNK (TT / SPLITS)   // 64

// Output layout (float32): context[B,CD] | a[B,T] | u_new[B] | sq_new[B]
#define CTX_OFF 0
#define A_OFF   (BB * CD)                 // 32768
#define U_OFF   (A_OFF + BB * TT)         // 98304
#define SQ_OFF  (U_OFF + BB)              // 98368

// Scratch: partial (unnormalized) contexts and partial v-sums
__device__ float g_partial[BB * SPLITS * CD];
__device__ float g_vsum[BB * SPLITS];

__device__ __forceinline__ float alpha_v(
    const float* __restrict__ arow, int t, float ub, float sqb)
{
    const float cur  = arow[t];
    const float prev = (t > 0) ? arow[t - 1] : 0.0f;
    const float base = fmaf(-ub, cur, cur) + fmaf(ub, prev, 1e-6f);
    return __expf(sqb * __logf(base));   // base > 0 always
}

// ---------------------------------------------------------------------------
// K2: fused alpha + split-T partial context. Grid (SPLITS, B), 128 threads.
// Threads 0..63 compute the chunk's unnormalized v into smem; warp 0 records
// the chunk v-sum. All 128 threads stream the 64xCD input slab via float4
// (__ldcs, read-once) into 4 independent accumulators -> partial context.
// No writes to the 'a' region here (K3 recomputes v and writes normalized).
// ---------------------------------------------------------------------------
__global__ void __launch_bounds__(128) k_context_partial(
    const float* __restrict__ inputs,
    const float* __restrict__ alpha,
    const float* __restrict__ u,
    const float* __restrict__ sq,
    float* __restrict__ partial,
    float* __restrict__ vsum)
{
    const int s   = blockIdx.x;
    const int b   = blockIdx.y;
    const int tid = threadIdx.x;
    const int t0  = s * TCHUNK;

    __shared__ float sa[TCHUNK];

    if (tid < TCHUNK) {
        const float ub  = u[b];
        const float sqb = sq[b];
        sa[tid] = alpha_v(alpha + (size_t)b * TT, t0 + tid, ub, sqb);
    }
    __syncthreads();

    if (tid < 32) {  // warp 0: chunk v-sum (deterministic order)
        float x = sa[tid] + sa[tid + 32];
        #pragma unroll
        for (int o = 16; o > 0; o >>= 1) x += __shfl_xor_sync(0xffffffffu, x, o);
        if (tid == 0) vsum[(size_t)b * SPLITS + s] = x;
    }

    const float4* __restrict__ inp =
        (const float4*)(inputs + ((size_t)b * TT + t0) * CD) + tid;

    float4 a0 = {0,0,0,0}, a1 = {0,0,0,0}, a2 = {0,0,0,0}, a3 = {0,0,0,0};
    #pragma unroll 4
    for (int i = 0; i < TCHUNK; i += 4) {
        const float4 v0 = __ldcs(&inp[(size_t)(i + 0) * (CD/4)]);
        const float4 v1 = __ldcs(&inp[(size_t)(i + 1) * (CD/4)]);
        const float4 v2 = __ldcs(&inp[(size_t)(i + 2) * (CD/4)]);
        const float4 v3 = __ldcs(&inp[(size_t)(i + 3) * (CD/4)]);
        const float w0 = sa[i + 0], w1 = sa[i + 1], w2 = sa[i + 2], w3 = sa[i + 3];
        a0.x = fmaf(w0, v0.x, a0.x); a0.y = fmaf(w0, v0.y, a0.y);
        a0.z = fmaf(w0, v0.z, a0.z); a0.w = fmaf(w0, v0.w, a0.w);
        a1.x = fmaf(w1, v1.x, a1.x); a1.y = fmaf(w1, v1.y, a1.y);
        a1.z = fmaf(w1, v1.z, a1.z); a1.w = fmaf(w1, v1.w, a1.w);
        a2.x = fmaf(w2, v2.x, a2.x); a2.y = fmaf(w2, v2.y, a2.y);
        a2.z = fmaf(w2, v2.z, a2.z); a2.w = fmaf(w2, v2.w, a2.w);
        a3.x = fmaf(w3, v3.x, a3.x); a3.y = fmaf(w3, v3.y, a3.y);
        a3.z = fmaf(w3, v3.z, a3.z); a3.w = fmaf(w3, v3.w, a3.w);
    }
    float4 r;
    r.x = (a0.x + a1.x) + (a2.x + a3.x);
    r.y = (a0.y + a1.y) + (a2.y + a3.y);
    r.z = (a0.z + a1.z) + (a2.z + a3.z);
    r.w = (a0.w + a1.w) + (a2.w + a3.w);
    ((float4*)(partial + ((size_t)b * SPLITS + s) * CD))[tid] = r;
}

// ---------------------------------------------------------------------------
// K3: grid (2, B), 128 threads. Both roles first get S from the 16 vsums.
// role 0: float4-reduce 16 partials -> normalized context; heads via shuffle
//         reductions (2 sync points total).
// role 1: recompute v from alpha and write normalized 'a' directly.
// ---------------------------------------------------------------------------
__global__ void __launch_bounds__(128) k_finish(
    const float* __restrict__ partial,
    const float* __restrict__ vsum,
    const float* __restrict__ alpha,
    const float* __restrict__ u,
    const float* __restrict__ sq,
    const float* __restrict__ query,
    const float* __restrict__ W_u,  const float* __restrict__ b_u,
    const float* __restrict__ W_sq, const float* __restrict__ b_sq,
    float* __restrict__ out)
{
    const int role = blockIdx.x;
    const int b    = blockIdx.y;
    const int tid  = threadIdx.x;
    const int lane = tid & 31;
    const int wid  = tid >> 5;

    // S = sum of 16 chunk sums (every thread; L2 hits)
    float S = 0.0f;
    #pragma unroll
    for (int k = 0; k < SPLITS; k++) S += vsum[(size_t)b * SPLITS + k];
    const float inv = 1.0f / S;

    if (role == 1) {
        // normalized 'a': 1024 elems, 128 threads -> 8 each
        const float ub  = u[b];
        const float sqb = sq[b];
        const float* arow = alpha + (size_t)b * TT;
        #pragma unroll
        for (int t = tid; t < TT; t += 128)
            out[A_OFF + (size_t)b * TT + t] = alpha_v(arow, t, ub, sqb) * inv;
        return;
    }

    // role 0: context + heads. Thread owns float4 column group tid (128 groups).
    const float4* __restrict__ p4 = (const float4*)(partial + (size_t)b * SPLITS * CD);
    float4 acc = {0,0,0,0};
    #pragma unroll
    for (int k = 0; k < SPLITS; k++) {
        const float4 v = p4[(size_t)k * (CD/4) + tid];
        acc.x += v.x; acc.y += v.y; acc.z += v.z; acc.w += v.w;
    }
    acc.x *= inv; acc.y *= inv; acc.z *= inv; acc.w *= inv;
    ((float4*)(out + CTX_OFF + (size_t)b * CD))[tid] = acc;

    // heads: ta = [context(512), query(1024)], W rows match that order.
    const float4 wu_c = ((const float4*)W_u)[tid];
    const float4 ws_c = ((const float4*)W_sq)[tid];
    float pu = acc.x * wu_c.x + acc.y * wu_c.y + acc.z * wu_c.z + acc.w * wu_c.w;
    float ps = acc.x * ws_c.x + acc.y * ws_c.y + acc.z * ws_c.z + acc.w * ws_c.w;

    const float4* __restrict__ q4 = (const float4*)(query + (size_t)b * QD);
    #pragma unroll
    for (int j = 0; j < 2; j++) {
        const int i = j * 128 + tid;                 // float4 index into query
        const float4 q  = q4[i];
        const float4 wu = ((const float4*)(W_u  + CD))[i];
        const float4 ws = ((const float4*)(W_sq + CD))[i];
        pu += q.x * wu.x + q.y * wu.y + q.z * wu.z + q.w * wu.w;
        ps += q.x * ws.x + q.y * ws.y + q.z * ws.z + q.w * ws.w;
    }

    #pragma unroll
    for (int o = 16; o > 0; o >>= 1) {
        pu += __shfl_xor_sync(0xffffffffu, pu, o);
        ps += __shfl_xor_sync(0xffffffffu, ps, o);
    }
    __shared__ float ru[4], rs[4];
    if (lane == 0) { ru[wid] = pu; rs[wid] = ps; }
    __syncthreads();
    if (tid == 0) {
        const float PU = (ru[0] + ru[1]) + (ru[2] + ru[3]);
        const float PS = (rs[0] + rs[1]) + (rs[2] + rs[3]);
        out[U_OFF + b]  = 1.0f / (1.0f + expf(-(PU + b_u[0])));
        out[SQ_OFF + b] = 1.0f / (1.0f + expf(-(PS + b_sq[0]))) + 1.0f;
    }
}

extern "C" void kernel_launch(void* const* d_in, const int* in_sizes, int n_in,
                              void* d_out, int out_size)
{
    const float* query  = (const float*)d_in[0];  // [B,1,QD]
    const float* inputs = (const float*)d_in[1];  // [B,T,CD]
    const float* alpha  = (const float*)d_in[2];  // [B,T]
    const float* u      = (const float*)d_in[3];  // [B,1]
    const float* sq     = (const float*)d_in[4];  // [B,1]
    const float* W_u    = (const float*)d_in[5];  // [QD+CD,1]
    const float* b_u    = (const float*)d_in[6];  // [1]
    const float* W_sq   = (const float*)d_in[7];  // [QD+CD,1]
    const float* b_sq   = (const float*)d_in[8];  // [1]
    float* out = (float*)d_out;

    float* partial;
    float* vsum;
    cudaGetSymbolAddress((void**)&partial, g_partial);
    cudaGetSymbolAddress((void**)&vsum, g_vsum);

    dim3 g2(SPLITS, BB);
    k_context_partial<<<g2, 128>>>(inputs, alpha, u, sq, partial, vsum);

    dim3 g3(2, BB);
    k_finish<<<g3, 128>>>(partial, vsum, alpha, u, sq, query,
                          W_u, b_u, W_sq, b_sq, out);
}